// round 1
// baseline (speedup 1.0000x reference)
#include <cuda_runtime.h>
#include <mma.h>

using namespace nvcuda;

// Problem constants
#define Bb 2
#define Ss 2048
#define DModel 1024
#define Hh 16
#define Dh 64

// Scratch for projected Q/K/V in [B,H,S,Dh] layout (16 MB each)
__device__ float g_qw[Bb*Hh*Ss*Dh];
__device__ float g_kw[Bb*Hh*Ss*Dh];
__device__ float g_vw[Bb*Hh*Ss*Dh];

// ---------------------------------------------------------------------------
// Projection GEMM: Y[m,n] = X[m,:] @ W[:,n] + bias[n], written as [B,H,S,Dh]
// Block tile 128x64, K-tile 32, 8 warps, wmma tf32 m16n16k8.
// ---------------------------------------------------------------------------
#define PBM 128
#define PBN 64
#define PBK 32
#define PLDA 36
#define PLDB 72

__global__ __launch_bounds__(256) void proj_kernel(
    const float* __restrict__ X, const float* __restrict__ W,
    const float* __restrict__ bias, int which)
{
    __shared__ __align__(32) float sA[PBM*PLDA];
    __shared__ __align__(32) float sB[PBK*PLDB];
    float* Y = (which==0) ? g_qw : (which==1) ? g_kw : g_vw;

    int tid  = threadIdx.x;
    int warp = tid >> 5, lane = tid & 31;
    int m0 = blockIdx.x * PBM;
    int n0 = blockIdx.y * PBN;
    int wm = warp >> 1, wn = warp & 1;   // 4x2 warp grid, 32x32 per warp

    wmma::fragment<wmma::accumulator,16,16,8,float> acc[2][2];
    #pragma unroll
    for (int i=0;i<2;i++)
      #pragma unroll
      for (int j=0;j<2;j++) wmma::fill_fragment(acc[i][j], 0.0f);

    for (int k0 = 0; k0 < DModel; k0 += PBK) {
        // A tile: 128x32, 256 threads x 4 float4
        #pragma unroll
        for (int p = 0; p < 4; p++) {
            int r = p*32 + (tid >> 3);
            int c = (tid & 7) << 2;
            *(float4*)&sA[r*PLDA + c] =
                *(const float4*)&X[(m0 + r)*DModel + k0 + c];
        }
        // B tile: 32x64, 256 threads x 2 float4
        #pragma unroll
        for (int p = 0; p < 2; p++) {
            int r = p*16 + (tid >> 4);
            int c = (tid & 15) << 2;
            *(float4*)&sB[r*PLDB + c] =
                *(const float4*)&W[(k0 + r)*DModel + n0 + c];
        }
        __syncthreads();

        #pragma unroll
        for (int kk = 0; kk < PBK; kk += 8) {
            wmma::fragment<wmma::matrix_a,16,16,8,wmma::precision::tf32,wmma::row_major> af[2];
            wmma::fragment<wmma::matrix_b,16,16,8,wmma::precision::tf32,wmma::row_major> bf[2];
            #pragma unroll
            for (int i=0;i<2;i++) {
                wmma::load_matrix_sync(af[i], &sA[(wm*32 + i*16)*PLDA + kk], PLDA);
                #pragma unroll
                for (int t=0;t<af[i].num_elements;t++)
                    af[i].x[t] = wmma::__float_to_tf32(af[i].x[t]);
            }
            #pragma unroll
            for (int j=0;j<2;j++) {
                wmma::load_matrix_sync(bf[j], &sB[kk*PLDB + wn*32 + j*16], PLDB);
                #pragma unroll
                for (int t=0;t<bf[j].num_elements;t++)
                    bf[j].x[t] = wmma::__float_to_tf32(bf[j].x[t]);
            }
            #pragma unroll
            for (int i=0;i<2;i++)
                #pragma unroll
                for (int j=0;j<2;j++)
                    wmma::mma_sync(acc[i][j], af[i], bf[j], acc[i][j]);
        }
        __syncthreads();
    }

    // Epilogue: stage each 16x16 frag through smem, add bias, write to
    // [B,H,S,Dh] layout. n-tile of 64 == exactly one head.
    int bb = m0 >> 11;             // batch (2048 rows per batch, 128 | 2048)
    int s_base = m0 & (Ss-1);
    int h = n0 >> 6;
    float* outb = Y + ((bb*Hh + h)*Ss) * Dh;
    float* stage = &sB[warp * 256];   // 16x16 per warp, reuse sB after sync

    #pragma unroll
    for (int i=0;i<2;i++) {
      #pragma unroll
      for (int j=0;j<2;j++) {
        wmma::store_matrix_sync(stage, acc[i][j], 16, wmma::mem_row_major);
        __syncwarp();
        int rb = wm*32 + i*16;
        int cb = wn*32 + j*16;
        #pragma unroll
        for (int p=0;p<8;p++) {
            int rr = p*2 + (lane >> 4);
            int cc = lane & 15;
            outb[(s_base + rb + rr)*Dh + cb + cc] =
                stage[rr*16 + cc] + bias[n0 + cb + cc];
        }
        __syncwarp();
      }
    }
}

// ---------------------------------------------------------------------------
// Flash attention: per (b,h), Q-tile 64 x KV-tiles of 64, online softmax.
// 4 warps (128 threads). QK^T and PV via wmma tf32; softmax SIMT via smem.
// ---------------------------------------------------------------------------
#define TQ 64
#define TK 64
#define ALD 72

__global__ __launch_bounds__(128) void attn_kernel(
    const int* __restrict__ v_mask, const int* __restrict__ q_mask,
    float* __restrict__ out)
{
    extern __shared__ __align__(32) float sm[];
    float* sQ = sm;                 // 64 x 72
    float* sK = sQ + TQ*ALD;        // 64 x 72
    float* sV = sK + TK*ALD;        // 64 x 72
    float* sS = sV + TK*ALD;        // 64 x 72 (scores -> P -> PV result)
    float* sResc = sS + TQ*ALD;     // 64
    float* sL    = sResc + 64;      // 64

    int tid  = threadIdx.x;
    int warp = tid >> 5;
    int bh = blockIdx.y;            // b*16 + h
    int b  = bh >> 4;
    int q0 = blockIdx.x * TQ;

    const float* Qg = g_qw + (bh*Ss + q0)*Dh;
    const float* Kg = g_kw + bh*Ss*Dh;
    const float* Vg = g_vw + bh*Ss*Dh;

    // Load Q tile, pre-scaled by 1/sqrt(64)
    #pragma unroll
    for (int i = tid; i < TQ*Dh/4; i += 128) {
        int r = i >> 4;
        int c = (i & 15) << 2;
        float4 v4 = *(const float4*)&Qg[r*Dh + c];
        v4.x *= 0.125f; v4.y *= 0.125f; v4.z *= 0.125f; v4.w *= 0.125f;
        *(float4*)&sQ[r*ALD + c] = v4;
    }

    // O accumulator: thread owns (row = tid&63, 32 cols starting at (tid>>6)*32)
    float o[32];
    #pragma unroll
    for (int j=0;j<32;j++) o[j] = 0.f;
    int r_o = tid & 63;
    int c0  = (tid >> 6) * 32;

    // Row stats live in registers of threads tid<64 (thread t owns row t)
    float mreg = -3.0e38f, lreg = 0.f;

    for (int kv0 = 0; kv0 < Ss; kv0 += TK) {
        // Load K and V tiles
        #pragma unroll
        for (int i = tid; i < TK*Dh/4; i += 128) {
            int r = i >> 4;
            int c = (i & 15) << 2;
            *(float4*)&sK[r*ALD + c] = *(const float4*)&Kg[(kv0 + r)*Dh + c];
            *(float4*)&sV[r*ALD + c] = *(const float4*)&Vg[(kv0 + r)*Dh + c];
        }
        __syncthreads();

        // S = Q K^T  (each warp: 16 q-rows x 64 kv-cols)
        {
            wmma::fragment<wmma::accumulator,16,16,8,float> acc[4];
            #pragma unroll
            for (int c=0;c<4;c++) wmma::fill_fragment(acc[c], 0.f);
            #pragma unroll
            for (int kk=0; kk<Dh; kk+=8) {
                wmma::fragment<wmma::matrix_a,16,16,8,wmma::precision::tf32,wmma::row_major> af;
                wmma::load_matrix_sync(af, &sQ[(warp*16)*ALD + kk], ALD);
                #pragma unroll
                for (int t=0;t<af.num_elements;t++) af.x[t]=wmma::__float_to_tf32(af.x[t]);
                #pragma unroll
                for (int c=0;c<4;c++) {
                    // K^T as col_major view of row-major K tile
                    wmma::fragment<wmma::matrix_b,16,16,8,wmma::precision::tf32,wmma::col_major> bf;
                    wmma::load_matrix_sync(bf, &sK[(c*16)*ALD + kk], ALD);
                    #pragma unroll
                    for (int t=0;t<bf.num_elements;t++) bf.x[t]=wmma::__float_to_tf32(bf.x[t]);
                    wmma::mma_sync(acc[c], af, bf, acc[c]);
                }
            }
            #pragma unroll
            for (int c=0;c<4;c++)
                wmma::store_matrix_sync(&sS[(warp*16)*ALD + c*16], acc[c], ALD,
                                        wmma::mem_row_major);
        }
        __syncthreads();

        // Online softmax over this tile (thread t<64 owns row t)
        if (tid < 64) {
            int r = tid;
            float tm = -3.0e38f;
            #pragma unroll 8
            for (int c=0;c<TK;c++) {
                float x = sS[r*ALD + c]
                        - (1.0f - (float)v_mask[b*Ss + kv0 + c]) * 1e10f;
                sS[r*ALD + c] = x;
                tm = fmaxf(tm, x);
            }
            float newm  = fmaxf(mreg, tm);
            float alpha = __expf(mreg - newm);
            float sum = 0.f;
            #pragma unroll 8
            for (int c=0;c<TK;c++) {
                float p = __expf(sS[r*ALD + c] - newm);
                sS[r*ALD + c] = p;
                sum += p;
            }
            lreg = lreg*alpha + sum;
            mreg = newm;
            sResc[r] = alpha;
        }
        __syncthreads();

        // PV = P @ V (P in sS), result staged back into sS
        {
            wmma::fragment<wmma::accumulator,16,16,8,float> acc[4];
            #pragma unroll
            for (int c=0;c<4;c++) wmma::fill_fragment(acc[c], 0.f);
            #pragma unroll
            for (int kk=0; kk<TK; kk+=8) {
                wmma::fragment<wmma::matrix_a,16,16,8,wmma::precision::tf32,wmma::row_major> af;
                wmma::load_matrix_sync(af, &sS[(warp*16)*ALD + kk], ALD);
                #pragma unroll
                for (int t=0;t<af.num_elements;t++) af.x[t]=wmma::__float_to_tf32(af.x[t]);
                #pragma unroll
                for (int c=0;c<4;c++) {
                    wmma::fragment<wmma::matrix_b,16,16,8,wmma::precision::tf32,wmma::row_major> bf;
                    wmma::load_matrix_sync(bf, &sV[kk*ALD + c*16], ALD);
                    #pragma unroll
                    for (int t=0;t<bf.num_elements;t++) bf.x[t]=wmma::__float_to_tf32(bf.x[t]);
                    wmma::mma_sync(acc[c], af, bf, acc[c]);
                }
            }
            __syncthreads();   // all warps done reading P from sS
            #pragma unroll
            for (int c=0;c<4;c++)
                wmma::store_matrix_sync(&sS[(warp*16)*ALD + c*16], acc[c], ALD,
                                        wmma::mem_row_major);
        }
        __syncthreads();

        // O = O*alpha + PV
        {
            float al = sResc[r_o];
            #pragma unroll
            for (int j=0;j<32;j++)
                o[j] = o[j]*al + sS[r_o*ALD + c0 + j];
        }
        __syncthreads();
    }

    if (tid < 64) sL[tid] = lreg;
    __syncthreads();

    // Final: divide by l, apply q_mask, write [B,S,H*Dh]
    int s = q0 + r_o;
    float f = (1.0f / sL[r_o]) * (float)q_mask[b*Ss + s];
    int h = bh & 15;
    float* op = out + (b*Ss + s)*DModel + h*Dh + c0;
    #pragma unroll
    for (int j=0;j<32;j++) op[j] = o[j]*f;
}

// ---------------------------------------------------------------------------
extern "C" void kernel_launch(void* const* d_in, const int* in_sizes, int n_in,
                              void* d_out, int out_size) {
    const float* q  = (const float*)d_in[0];
    const float* k  = (const float*)d_in[1];
    const float* v  = (const float*)d_in[2];
    const int*   vm = (const int*)d_in[3];
    const int*   qm = (const int*)d_in[4];
    const float* Wq = (const float*)d_in[5];
    const float* bq = (const float*)d_in[6];
    const float* Wk = (const float*)d_in[7];
    const float* bk = (const float*)d_in[8];
    const float* Wv = (const float*)d_in[9];
    const float* bv = (const float*)d_in[10];
    float* out = (float*)d_out;

    const int attn_smem = (4*TQ*ALD + 128) * (int)sizeof(float);  // 74240 B
    cudaFuncSetAttribute(attn_kernel,
                         cudaFuncAttributeMaxDynamicSharedMemorySize, attn_smem);

    dim3 pg(Bb*Ss/PBM, DModel/PBN);   // (32, 16)
    proj_kernel<<<pg, 256>>>(q, Wq, bq, 0);
    proj_kernel<<<pg, 256>>>(k, Wk, bk, 1);
    proj_kernel<<<pg, 256>>>(v, Wv, bv, 2);

    dim3 ag(Ss/TQ, Bb*Hh);            // (32, 32)
    attn_kernel<<<ag, 128, attn_smem>>>(vm, qm, out);
}

// round 2
// speedup vs baseline: 3.7648x; 3.7648x over previous
#include <cuda_runtime.h>
#include <cuda_fp16.h>
#include <cstdint>

// Problem constants
#define Bb 2
#define Ss 2048
#define DModel 1024
#define Hh 16
#define Dh 64

// fp16 scratch: Q,K in [B,H,S,Dh]; V transposed [B,H,Dh,S]
__device__ __align__(256) __half g_qh[Bb*Hh*Ss*Dh];
__device__ __align__(256) __half g_kh[Bb*Hh*Ss*Dh];
__device__ __align__(256) __half g_vth[Bb*Hh*Dh*Ss];

// ---------------------------------------------------------------------------
// Helpers
// ---------------------------------------------------------------------------
__device__ __forceinline__ uint32_t smem_u32(const void* p) {
    return (uint32_t)__cvta_generic_to_shared(p);
}
__device__ __forceinline__ void cp16(uint32_t s, const void* g) {
    asm volatile("cp.async.cg.shared.global [%0], [%1], 16;\n" :: "r"(s), "l"(g));
}
#define CP_COMMIT asm volatile("cp.async.commit_group;\n")
template<int N> __device__ __forceinline__ void cp_wait() {
    asm volatile("cp.async.wait_group %0;\n" :: "n"(N));
}
// D += A*B, m16n8k16 fp16 in / fp32 acc
__device__ __forceinline__ void mma16816(float* d, const uint32_t* a, const uint32_t* b) {
    asm volatile(
        "mma.sync.aligned.m16n8k16.row.col.f32.f16.f16.f32 "
        "{%0,%1,%2,%3},{%4,%5,%6,%7},{%8,%9},{%0,%1,%2,%3};\n"
        : "+f"(d[0]), "+f"(d[1]), "+f"(d[2]), "+f"(d[3])
        : "r"(a[0]), "r"(a[1]), "r"(a[2]), "r"(a[3]), "r"(b[0]), "r"(b[1]));
}
__device__ __forceinline__ uint32_t f22u(float x, float y) {
    __half2 h = __floats2half2_rn(x, y);
    return *reinterpret_cast<uint32_t*>(&h);
}

// ---------------------------------------------------------------------------
// Fused QKV projection: Y = X @ W + b, fp16-mma, cp.async double buffer.
// Block tile 128(m) x 64(n), k-tile 32, 8 warps (4x2), warp tile 32x32.
// z=0: Q (scaled 0.125) -> g_qh [bh][s][d]
// z=1: K               -> g_kh [bh][s][d]
// z=2: V               -> g_vth [bh][d][s]  (transposed at store)
// ---------------------------------------------------------------------------
#define PA_LD 36
#define PB_LD 68

__global__ __launch_bounds__(256) void proj_kernel(
    const float* __restrict__ q, const float* __restrict__ k, const float* __restrict__ v,
    const float* __restrict__ Wq, const float* __restrict__ bq,
    const float* __restrict__ Wk, const float* __restrict__ bk,
    const float* __restrict__ Wv, const float* __restrict__ bv)
{
    extern __shared__ __align__(16) float psm[];
    float* sA = psm;                  // 2 x 128 x 36
    float* sB = psm + 2*128*PA_LD;    // 2 x 32 x 68

    const int z = blockIdx.z;
    const float* X    = (z==0) ? q  : (z==1) ? k  : v;
    const float* W    = (z==0) ? Wq : (z==1) ? Wk : Wv;
    const float* bias = (z==0) ? bq : (z==1) ? bk : bv;

    const int tid = threadIdx.x;
    const int warp = tid >> 5, lane = tid & 31;
    const int wm = warp >> 1, wn = warp & 1;
    const int r0 = lane >> 2, qp = lane & 3;
    const int m0 = blockIdx.x * 128, n0 = blockIdx.y * 64;

    float acc[2][4][4];
    #pragma unroll
    for (int mi=0;mi<2;mi++)
        #pragma unroll
        for (int ni=0;ni<4;ni++)
            #pragma unroll
            for (int c=0;c<4;c++) acc[mi][ni][c] = 0.f;

    const uint32_t sab = smem_u32(sA), sbb = smem_u32(sB);

    auto issue = [&](int buf, int kt) {
        #pragma unroll
        for (int p=0;p<4;p++) {                 // A: 128x32 f32 = 1024 chunks
            int ch = tid + p*256;
            int row = ch >> 3, co = ch & 7;
            cp16(sab + buf*(128*PA_LD*4) + row*(PA_LD*4) + co*16,
                 X + (m0+row)*DModel + kt*32 + co*4);
        }
        #pragma unroll
        for (int p=0;p<2;p++) {                 // B: 32x64 f32 = 512 chunks
            int ch = tid + p*256;
            int row = ch >> 4, co = ch & 15;
            cp16(sbb + buf*(32*PB_LD*4) + row*(PB_LD*4) + co*16,
                 W + (kt*32+row)*DModel + n0 + co*4);
        }
    };

    issue(0, 0); CP_COMMIT;

    for (int kt = 0; kt < 32; kt++) {
        const int buf = kt & 1;
        if (kt < 31) { issue(buf^1, kt+1); CP_COMMIT; cp_wait<1>(); }
        else         { cp_wait<0>(); }
        __syncthreads();

        const float* A  = sA + buf*128*PA_LD;
        const float* Bm = sB + buf*32*PB_LD;

        #pragma unroll
        for (int ks = 0; ks < 32; ks += 16) {
            uint32_t af[2][4];
            #pragma unroll
            for (int mi=0;mi<2;mi++) {
                const float* ap = A + (wm*32 + mi*16 + r0)*PA_LD + ks + qp*2;
                float2 v0 = *(const float2*)ap;
                float2 v1 = *(const float2*)(ap + 8*PA_LD);
                float2 v2 = *(const float2*)(ap + 8);
                float2 v3 = *(const float2*)(ap + 8*PA_LD + 8);
                af[mi][0]=f22u(v0.x,v0.y); af[mi][1]=f22u(v1.x,v1.y);
                af[mi][2]=f22u(v2.x,v2.y); af[mi][3]=f22u(v3.x,v3.y);
            }
            #pragma unroll
            for (int ni=0;ni<4;ni++) {
                const float* bp = Bm + (ks + qp*2)*PB_LD + wn*32 + ni*8 + r0;
                uint32_t bfr[2];
                bfr[0] = f22u(bp[0],        bp[PB_LD]);
                bfr[1] = f22u(bp[8*PB_LD],  bp[9*PB_LD]);
                #pragma unroll
                for (int mi=0;mi<2;mi++) mma16816(acc[mi][ni], af[mi], bfr);
            }
        }
        __syncthreads();
    }

    // Epilogue: add bias, convert fp16, store to scratch layouts
    const int b = m0 >> 11, h = n0 >> 6;
    const int sbase = (m0 & (Ss-1)) + wm*32;

    if (z < 2) {
        const float scale = (z==0) ? 0.125f : 1.0f;
        __half* G = ((z==0) ? g_qh : g_kh) + (b*Hh + h)*Ss*Dh;
        #pragma unroll
        for (int mi=0;mi<2;mi++) {
            int sr = sbase + mi*16 + r0;
            #pragma unroll
            for (int ni=0;ni<4;ni++) {
                int col = wn*32 + ni*8 + qp*2;
                float2 bb = *(const float2*)&bias[n0 + col];
                __half2 h0 = __floats2half2_rn((acc[mi][ni][0]+bb.x)*scale,
                                               (acc[mi][ni][1]+bb.y)*scale);
                __half2 h1 = __floats2half2_rn((acc[mi][ni][2]+bb.x)*scale,
                                               (acc[mi][ni][3]+bb.y)*scale);
                *(__half2*)&G[ sr   *Dh + col] = h0;
                *(__half2*)&G[(sr+8)*Dh + col] = h1;
            }
        }
    } else {
        __half* G = g_vth + (b*Hh + h)*Dh*Ss;
        #pragma unroll
        for (int mi=0;mi<2;mi++) {
            int sr = sbase + mi*16 + r0;
            #pragma unroll
            for (int ni=0;ni<4;ni++) {
                int col = wn*32 + ni*8 + qp*2;
                float2 bb = *(const float2*)&bias[n0 + col];
                G[ col   *Ss + sr  ] = __float2half(acc[mi][ni][0]+bb.x);
                G[(col+1)*Ss + sr  ] = __float2half(acc[mi][ni][1]+bb.y);
                G[ col   *Ss + sr+8] = __float2half(acc[mi][ni][2]+bb.x);
                G[(col+1)*Ss + sr+8] = __float2half(acc[mi][ni][3]+bb.y);
            }
        }
    }
}

// ---------------------------------------------------------------------------
// Flash attention: Q-tile 128 (8 warps x 16 rows), KV-tile 64, fp16 mma,
// S/P fully register-resident, cp.async double-buffered K/V tiles.
// ---------------------------------------------------------------------------
#define AK_LD 72   // fp16 elements per smem row (64 + 8 pad)

__global__ __launch_bounds__(256,2) void attn_kernel(
    const int* __restrict__ v_mask, const int* __restrict__ q_mask,
    float* __restrict__ out)
{
    __shared__ __align__(16) __half sK[2][64*AK_LD];
    __shared__ __align__(16) __half sV[2][64*AK_LD];
    __shared__ float sBias[2][64];

    const int tid = threadIdx.x;
    const int warp = tid >> 5, lane = tid & 31;
    const int r0 = lane >> 2, qp = lane & 3;
    const int bh = blockIdx.y, b = bh >> 4;
    const int q0 = blockIdx.x * 128;
    const int rq = warp * 16;

    const __half* gQ = g_qh + (bh*Ss + q0 + rq)*Dh;
    const __half* gK = g_kh + bh*Ss*Dh;
    const __half* gV = g_vth + bh*Dh*Ss;

    // Persistent Q fragments (A operand): 4 k-tiles of 16
    uint32_t qf[4][4];
    #pragma unroll
    for (int kt=0;kt<4;kt++) {
        int k0 = kt*16 + qp*2;
        qf[kt][0] = *(const uint32_t*)&gQ[(r0  )*Dh + k0];
        qf[kt][1] = *(const uint32_t*)&gQ[(r0+8)*Dh + k0];
        qf[kt][2] = *(const uint32_t*)&gQ[(r0  )*Dh + k0+8];
        qf[kt][3] = *(const uint32_t*)&gQ[(r0+8)*Dh + k0+8];
    }

    float o[8][4];
    #pragma unroll
    for (int nt=0;nt<8;nt++)
        #pragma unroll
        for (int c=0;c<4;c++) o[nt][c] = 0.f;
    float m0v = -1e30f, m1v = -1e30f, l0 = 0.f, l1 = 0.f;

    const uint32_t skb = smem_u32(sK), svb = smem_u32(sV);

    auto issue = [&](int buf, int kv0) {
        #pragma unroll
        for (int p=0;p<2;p++) {               // 512 chunks each for K and V
            int ch = tid + p*256;
            int row = ch >> 3, co = ch & 7;
            cp16(skb + buf*(64*AK_LD*2) + row*(AK_LD*2) + co*16,
                 gK + (kv0+row)*Dh + co*8);
            cp16(svb + buf*(64*AK_LD*2) + row*(AK_LD*2) + co*16,
                 gV + row*Ss + kv0 + co*8);
        }
    };

    int vreg = 0;
    if (tid < 64) vreg = v_mask[b*Ss + tid];
    issue(0, 0); CP_COMMIT;

    for (int t = 0; t < 32; t++) {
        const int buf = t & 1;
        const int kv0 = t * 64;
        if (tid < 64) sBias[buf][tid] = ((float)vreg - 1.0f) * 1e10f;
        if (t < 31) {
            issue(buf^1, kv0+64); CP_COMMIT;
            if (tid < 64) vreg = v_mask[b*Ss + kv0 + 64 + tid];
            cp_wait<1>();
        } else {
            cp_wait<0>();
        }
        __syncthreads();

        const __half* Kb = sK[buf];
        const __half* Vb = sV[buf];

        // S = Q K^T (16 x 64 per warp)
        float s[8][4];
        #pragma unroll
        for (int nt=0;nt<8;nt++)
            #pragma unroll
            for (int c=0;c<4;c++) s[nt][c] = 0.f;

        #pragma unroll
        for (int kt=0;kt<4;kt++) {
            #pragma unroll
            for (int nt=0;nt<8;nt++) {
                const __half* kp = &Kb[(nt*8 + r0)*AK_LD + kt*16 + qp*2];
                uint32_t bfr[2];
                bfr[0] = *(const uint32_t*)kp;
                bfr[1] = *(const uint32_t*)(kp + 8);
                mma16816(s[nt], qf[kt], bfr);
            }
        }

        // bias + row max (rows r0 and r0+8)
        float mx0 = -1e30f, mx1 = -1e30f;
        #pragma unroll
        for (int nt=0;nt<8;nt++) {
            float2 bb = *(const float2*)&sBias[buf][nt*8 + qp*2];
            s[nt][0] += bb.x; s[nt][1] += bb.y;
            s[nt][2] += bb.x; s[nt][3] += bb.y;
            mx0 = fmaxf(mx0, fmaxf(s[nt][0], s[nt][1]));
            mx1 = fmaxf(mx1, fmaxf(s[nt][2], s[nt][3]));
        }
        mx0 = fmaxf(mx0, __shfl_xor_sync(0xffffffffu, mx0, 1));
        mx0 = fmaxf(mx0, __shfl_xor_sync(0xffffffffu, mx0, 2));
        mx1 = fmaxf(mx1, __shfl_xor_sync(0xffffffffu, mx1, 1));
        mx1 = fmaxf(mx1, __shfl_xor_sync(0xffffffffu, mx1, 2));

        float nm0 = fmaxf(m0v, mx0), nm1 = fmaxf(m1v, mx1);
        float a0 = __expf(m0v - nm0), a1 = __expf(m1v - nm1);
        m0v = nm0; m1v = nm1;

        float sum0 = 0.f, sum1 = 0.f;
        #pragma unroll
        for (int nt=0;nt<8;nt++) {
            s[nt][0] = __expf(s[nt][0] - m0v);
            s[nt][1] = __expf(s[nt][1] - m0v);
            s[nt][2] = __expf(s[nt][2] - m1v);
            s[nt][3] = __expf(s[nt][3] - m1v);
            sum0 += s[nt][0] + s[nt][1];
            sum1 += s[nt][2] + s[nt][3];
        }
        sum0 += __shfl_xor_sync(0xffffffffu, sum0, 1);
        sum0 += __shfl_xor_sync(0xffffffffu, sum0, 2);
        sum1 += __shfl_xor_sync(0xffffffffu, sum1, 1);
        sum1 += __shfl_xor_sync(0xffffffffu, sum1, 2);
        l0 = l0*a0 + sum0;
        l1 = l1*a1 + sum1;

        // P -> fp16 A fragments (layout identity: S acc == PV A operand)
        uint32_t pf[4][4];
        #pragma unroll
        for (int kt=0;kt<4;kt++) {
            pf[kt][0] = f22u(s[2*kt  ][0], s[2*kt  ][1]);
            pf[kt][1] = f22u(s[2*kt  ][2], s[2*kt  ][3]);
            pf[kt][2] = f22u(s[2*kt+1][0], s[2*kt+1][1]);
            pf[kt][3] = f22u(s[2*kt+1][2], s[2*kt+1][3]);
        }

        // O rescale + O += P V
        #pragma unroll
        for (int nt=0;nt<8;nt++) {
            o[nt][0] *= a0; o[nt][1] *= a0;
            o[nt][2] *= a1; o[nt][3] *= a1;
        }
        #pragma unroll
        for (int kt=0;kt<4;kt++) {
            #pragma unroll
            for (int nt=0;nt<8;nt++) {
                const __half* vp = &Vb[(nt*8 + r0)*AK_LD + kt*16 + qp*2];
                uint32_t bfr[2];
                bfr[0] = *(const uint32_t*)vp;
                bfr[1] = *(const uint32_t*)(vp + 8);
                mma16816(o[nt], pf[kt], bfr);
            }
        }
        __syncthreads();
    }

    // Epilogue: O/l, q_mask, write [B,S,H*Dh] fp32
    const int s0 = q0 + rq + r0;
    const int s1 = s0 + 8;
    const float inv0 = (float)q_mask[b*Ss + s0] / l0;
    const float inv1 = (float)q_mask[b*Ss + s1] / l1;
    float* op0 = out + (b*Ss + s0)*DModel + (bh & 15)*Dh;
    float* op1 = out + (b*Ss + s1)*DModel + (bh & 15)*Dh;
    #pragma unroll
    for (int nt=0;nt<8;nt++) {
        int col = nt*8 + qp*2;
        float2 w0 = make_float2(o[nt][0]*inv0, o[nt][1]*inv0);
        float2 w1 = make_float2(o[nt][2]*inv1, o[nt][3]*inv1);
        *(float2*)&op0[col] = w0;
        *(float2*)&op1[col] = w1;
    }
}

// ---------------------------------------------------------------------------
extern "C" void kernel_launch(void* const* d_in, const int* in_sizes, int n_in,
                              void* d_out, int out_size) {
    const float* q  = (const float*)d_in[0];
    const float* k  = (const float*)d_in[1];
    const float* v  = (const float*)d_in[2];
    const int*   vm = (const int*)d_in[3];
    const int*   qm = (const int*)d_in[4];
    const float* Wq = (const float*)d_in[5];
    const float* bq = (const float*)d_in[6];
    const float* Wk = (const float*)d_in[7];
    const float* bk = (const float*)d_in[8];
    const float* Wv = (const float*)d_in[9];
    const float* bv = (const float*)d_in[10];
    float* out = (float*)d_out;

    const int proj_smem = (2*128*PA_LD + 2*32*PB_LD) * (int)sizeof(float);  // 54272
    cudaFuncSetAttribute(proj_kernel,
                         cudaFuncAttributeMaxDynamicSharedMemorySize, proj_smem);

    dim3 pg(Bb*Ss/128, DModel/64, 3);   // (32, 16, 3)
    proj_kernel<<<pg, 256, proj_smem>>>(q, k, v, Wq, bq, Wk, bk, Wv, bv);

    dim3 ag(Ss/128, Bb*Hh);             // (16, 32)
    attn_kernel<<<ag, 256>>>(vm, qm, out);
}

// round 4
// speedup vs baseline: 5.2385x; 1.3915x over previous
#include <cuda_runtime.h>
#include <cuda_fp16.h>
#include <cstdint>

// Problem constants
#define Bb 2
#define Ss 2048
#define DModel 1024
#define Hh 16
#define Dh 64
#define XN (Bb*Ss*DModel)   // 4194304
#define WN (DModel*DModel)  // 1048576

// fp16 copies of inputs
__device__ __align__(256) __half g_xq[XN], g_xk[XN], g_xv[XN];
__device__ __align__(256) __half g_wq[WN], g_wk[WN], g_wv[WN];
// fp16 projected Q,K,V all in [B,H,S,Dh]
__device__ __align__(256) __half g_qh[Bb*Hh*Ss*Dh];
__device__ __align__(256) __half g_kh[Bb*Hh*Ss*Dh];
__device__ __align__(256) __half g_vh[Bb*Hh*Ss*Dh];

// ---------------------------------------------------------------------------
// Helpers
// ---------------------------------------------------------------------------
__device__ __forceinline__ uint32_t smem_u32(const void* p) {
    return (uint32_t)__cvta_generic_to_shared(p);
}
__device__ __forceinline__ void cp16(uint32_t s, const void* g) {
    asm volatile("cp.async.cg.shared.global [%0], [%1], 16;\n" :: "r"(s), "l"(g));
}
#define CP_COMMIT asm volatile("cp.async.commit_group;\n")
template<int N> __device__ __forceinline__ void cp_wait() {
    asm volatile("cp.async.wait_group %0;\n" :: "n"(N));
}
__device__ __forceinline__ void mma16816(float* d, const uint32_t* a, const uint32_t* b) {
    asm volatile(
        "mma.sync.aligned.m16n8k16.row.col.f32.f16.f16.f32 "
        "{%0,%1,%2,%3},{%4,%5,%6,%7},{%8,%9},{%0,%1,%2,%3};\n"
        : "+f"(d[0]), "+f"(d[1]), "+f"(d[2]), "+f"(d[3])
        : "r"(a[0]), "r"(a[1]), "r"(a[2]), "r"(a[3]), "r"(b[0]), "r"(b[1]));
}
__device__ __forceinline__ void ldsm_x4(uint32_t* d, uint32_t a) {
    asm volatile("ldmatrix.sync.aligned.m8n8.x4.shared.b16 {%0,%1,%2,%3},[%4];\n"
        : "=r"(d[0]), "=r"(d[1]), "=r"(d[2]), "=r"(d[3]) : "r"(a));
}
__device__ __forceinline__ void ldsm_x4_t(uint32_t* d, uint32_t a) {
    asm volatile("ldmatrix.sync.aligned.m8n8.x4.trans.shared.b16 {%0,%1,%2,%3},[%4];\n"
        : "=r"(d[0]), "=r"(d[1]), "=r"(d[2]), "=r"(d[3]) : "r"(a));
}
__device__ __forceinline__ uint32_t f22u(float x, float y) {
    __half2 h = __floats2half2_rn(x, y);
    return *reinterpret_cast<uint32_t*>(&h);
}

// ---------------------------------------------------------------------------
// fp32 -> fp16 conversion (8 elems/thread), z selects tensor
// ---------------------------------------------------------------------------
__global__ __launch_bounds__(256) void cvt_kernel(
    const float* __restrict__ a, const float* __restrict__ b, const float* __restrict__ c,
    __half* __restrict__ oa, __half* __restrict__ ob, __half* __restrict__ oc)
{
    const int z = blockIdx.z;
    const float* in = (z==0) ? a : (z==1) ? b : c;
    __half* outp    = (z==0) ? oa : (z==1) ? ob : oc;
    int i = (blockIdx.x * 256 + threadIdx.x) * 8;
    float4 v0 = *(const float4*)&in[i];
    float4 v1 = *(const float4*)&in[i+4];
    uint4 w;
    w.x = f22u(v0.x, v0.y); w.y = f22u(v0.z, v0.w);
    w.z = f22u(v1.x, v1.y); w.w = f22u(v1.z, v1.w);
    *(uint4*)&outp[i] = w;
}

// ---------------------------------------------------------------------------
// QKV projection GEMM (fp16 in/out, fp32 acc): Y = X @ W + bias
// Block 128m x 128n, k-tile 32, 3-stage cp.async, 8 warps (4m x 2n), warp 32x64.
// z=0 -> g_qh (scaled 0.125), z=1 -> g_kh, z=2 -> g_vh. All [B,H,S,Dh].
// ---------------------------------------------------------------------------
#define GLDA 40    // halves per A smem row (32+8)
#define GLDB 136   // halves per B smem row (128+8)
#define GST 3

__global__ __launch_bounds__(256) void gemm_kernel(
    const float* __restrict__ bq, const float* __restrict__ bk, const float* __restrict__ bv)
{
    extern __shared__ __align__(16) __half gsm[];
    __half* sA = gsm;                      // GST x 128 x GLDA
    __half* sB = gsm + GST*128*GLDA;       // GST x 32 x GLDB

    const int z = blockIdx.z;
    const __half* X = (z==0) ? g_xq : (z==1) ? g_xk : g_xv;
    const __half* W = (z==0) ? g_wq : (z==1) ? g_wk : g_wv;
    const float* bias = (z==0) ? bq : (z==1) ? bk : bv;
    __half* G = (z==0) ? g_qh : (z==1) ? g_kh : g_vh;
    const float scale = (z==0) ? 0.125f : 1.0f;

    const int tid = threadIdx.x;
    const int warp = tid >> 5, lane = tid & 31;
    const int wm = warp >> 1, wn = warp & 1;
    const int r0 = lane >> 2, qp = lane & 3;
    const int m0 = blockIdx.x * 128, n0 = blockIdx.y * 128;

    float acc[2][8][4];
    #pragma unroll
    for (int mi=0;mi<2;mi++)
        #pragma unroll
        for (int ni=0;ni<8;ni++)
            #pragma unroll
            for (int c=0;c<4;c++) acc[mi][ni][c] = 0.f;

    const uint32_t sAu = smem_u32(sA), sBu = smem_u32(sB);
    // ldmatrix lane offsets (trans pattern: rows (l&7)+(l&8), col +16B if l>=16)
    const int lrow = (lane & 7) + (lane & 8);
    const int lcol = ((lane & 16) >> 4) * 16;

    auto issue = [&](int st, int kt) {
        #pragma unroll
        for (int p=0;p<2;p++) {            // A: 128x32 halves = 512 x 16B
            int ch = tid + p*256;
            int row = ch >> 2, co = ch & 3;
            cp16(sAu + (st*128 + row)*(GLDA*2) + co*16,
                 X + (m0+row)*DModel + kt*32 + co*8);
        }
        #pragma unroll
        for (int p=0;p<2;p++) {            // B: 32x128 halves = 512 x 16B
            int ch = tid + p*256;
            int row = ch >> 4, co = ch & 15;
            cp16(sBu + (st*32 + row)*(GLDB*2) + co*16,
                 W + (kt*32+row)*DModel + n0 + co*8);
        }
    };

    issue(0, 0); CP_COMMIT;
    issue(1, 1); CP_COMMIT;

    for (int kt = 0; kt < 32; kt++) {
        if (kt == 31) cp_wait<0>(); else cp_wait<1>();
        __syncthreads();
        if (kt < 30) { issue((kt+2)%GST, kt+2); CP_COMMIT; }

        const int st = kt % GST;
        const uint32_t Abase = sAu + st*128*(GLDA*2);
        const uint32_t Bbase = sBu + st*32*(GLDB*2);

        #pragma unroll
        for (int ks = 0; ks < 32; ks += 16) {
            uint32_t af[2][4];
            #pragma unroll
            for (int mi=0;mi<2;mi++)
                ldsm_x4(af[mi], Abase + (wm*32 + mi*16 + lrow)*(GLDA*2) + ks*2 + lcol);
            #pragma unroll
            for (int nn=0;nn<4;nn++) {
                uint32_t bf[4];
                ldsm_x4_t(bf, Bbase + (ks + lrow)*(GLDB*2) + (wn*64 + nn*16)*2 + lcol);
                #pragma unroll
                for (int mi=0;mi<2;mi++) {
                    mma16816(acc[mi][2*nn  ], af[mi], bf);
                    mma16816(acc[mi][2*nn+1], af[mi], bf+2);
                }
            }
        }
        __syncthreads();
    }

    // Epilogue: bias + scale, fp16 store to [B,H,S,Dh]
    const int b = m0 >> 11;
    const int h0 = (n0 >> 6) + wn;           // head for this warp's 64-col slab
    const int sbase = (m0 & (Ss-1)) + wm*32;
    __half* Gb = G + (b*Hh + h0)*Ss*Dh;
    #pragma unroll
    for (int mi=0;mi<2;mi++) {
        int sr = sbase + mi*16 + r0;
        #pragma unroll
        for (int ni=0;ni<8;ni++) {
            int col = ni*8 + qp*2;           // within head
            float2 bb = *(const float2*)&bias[n0 + wn*64 + col];
            *(__half2*)&Gb[ sr   *Dh + col] =
                __floats2half2_rn((acc[mi][ni][0]+bb.x)*scale, (acc[mi][ni][1]+bb.y)*scale);
            *(__half2*)&Gb[(sr+8)*Dh + col] =
                __floats2half2_rn((acc[mi][ni][2]+bb.x)*scale, (acc[mi][ni][3]+bb.y)*scale);
        }
    }
}

// ---------------------------------------------------------------------------
// Flash attention: Q-tile 128 (8 warps x 16 rows), KV-tile 64, fp16 mma,
// ldmatrix fragment loads, cp.async double-buffered K/V.
// ---------------------------------------------------------------------------
#define AK_LD 72   // halves per smem row (64 + 8)

__global__ __launch_bounds__(256,2) void attn_kernel(
    const int* __restrict__ v_mask, const int* __restrict__ q_mask,
    float* __restrict__ out)
{
    __shared__ __align__(16) __half sK[2][64*AK_LD];
    __shared__ __align__(16) __half sV[2][64*AK_LD];
    __shared__ float sBias[2][64];

    const int tid = threadIdx.x;
    const int warp = tid >> 5, lane = tid & 31;
    const int r0 = lane >> 2, qp = lane & 3;
    const int bh = blockIdx.y, b = bh >> 4;
    const int q0 = blockIdx.x * 128;
    const int rq = warp * 16;

    const __half* gQ = g_qh + (bh*Ss + q0 + rq)*Dh;
    const __half* gK = g_kh + bh*Ss*Dh;
    const __half* gV = g_vh + bh*Ss*Dh;

    // Persistent Q fragments
    uint32_t qf[4][4];
    #pragma unroll
    for (int kt=0;kt<4;kt++) {
        int k0 = kt*16 + qp*2;
        qf[kt][0] = *(const uint32_t*)&gQ[(r0  )*Dh + k0];
        qf[kt][1] = *(const uint32_t*)&gQ[(r0+8)*Dh + k0];
        qf[kt][2] = *(const uint32_t*)&gQ[(r0  )*Dh + k0+8];
        qf[kt][3] = *(const uint32_t*)&gQ[(r0+8)*Dh + k0+8];
    }

    float o[8][4];
    #pragma unroll
    for (int nt=0;nt<8;nt++)
        #pragma unroll
        for (int c=0;c<4;c++) o[nt][c] = 0.f;
    float m0v = -1e30f, m1v = -1e30f, l0 = 0.f, l1 = 0.f;

    const uint32_t skb = smem_u32(sK), svb = smem_u32(sV);
    // ldmatrix lane offsets
    const int lrowT = (lane & 7) + (lane & 8);            // trans pattern (V)
    const int lcolT = ((lane & 16) >> 4) * 16;
    const int lrowK = (lane & 7) + ((lane & 16) >> 1);    // non-trans paired-n (K)
    const int lcolK = (lane & 8) << 1;

    auto issue = [&](int buf, int kv0) {
        #pragma unroll
        for (int p=0;p<2;p++) {          // 512 x 16B each for K and V
            int ch = tid + p*256;
            int row = ch >> 3, co = ch & 7;
            cp16(skb + (buf*64 + row)*(AK_LD*2) + co*16, gK + (kv0+row)*Dh + co*8);
            cp16(svb + (buf*64 + row)*(AK_LD*2) + co*16, gV + (kv0+row)*Dh + co*8);
        }
    };

    int vreg = 0;
    if (tid < 64) vreg = v_mask[b*Ss + tid];
    issue(0, 0); CP_COMMIT;

    for (int t = 0; t < 32; t++) {
        const int buf = t & 1;
        const int kv0 = t * 64;
        if (tid < 64) sBias[buf][tid] = ((float)vreg - 1.0f) * 1e10f;
        if (t < 31) {
            issue(buf^1, kv0+64); CP_COMMIT;
            if (tid < 64) vreg = v_mask[b*Ss + kv0 + 64 + tid];
            cp_wait<1>();
        } else {
            cp_wait<0>();
        }
        __syncthreads();

        const uint32_t Kb = skb + buf*64*(AK_LD*2);
        const uint32_t Vb = svb + buf*64*(AK_LD*2);

        // S = Q K^T
        float s[8][4];
        #pragma unroll
        for (int nt=0;nt<8;nt++)
            #pragma unroll
            for (int c=0;c<4;c++) s[nt][c] = 0.f;

        #pragma unroll
        for (int kt=0;kt<4;kt++) {
            #pragma unroll
            for (int nn=0;nn<4;nn++) {
                uint32_t bf[4];
                ldsm_x4(bf, Kb + (nn*16 + lrowK)*(AK_LD*2) + kt*32 + lcolK);
                mma16816(s[2*nn  ], qf[kt], bf);
                mma16816(s[2*nn+1], qf[kt], bf+2);
            }
        }

        // bias + row max
        float mx0 = -1e30f, mx1 = -1e30f;
        #pragma unroll
        for (int nt=0;nt<8;nt++) {
            float2 bb = *(const float2*)&sBias[buf][nt*8 + qp*2];
            s[nt][0] += bb.x; s[nt][1] += bb.y;
            s[nt][2] += bb.x; s[nt][3] += bb.y;
            mx0 = fmaxf(mx0, fmaxf(s[nt][0], s[nt][1]));
            mx1 = fmaxf(mx1, fmaxf(s[nt][2], s[nt][3]));
        }
        mx0 = fmaxf(mx0, __shfl_xor_sync(0xffffffffu, mx0, 1));
        mx0 = fmaxf(mx0, __shfl_xor_sync(0xffffffffu, mx0, 2));
        mx1 = fmaxf(mx1, __shfl_xor_sync(0xffffffffu, mx1, 1));
        mx1 = fmaxf(mx1, __shfl_xor_sync(0xffffffffu, mx1, 2));

        float nm0 = fmaxf(m0v, mx0), nm1 = fmaxf(m1v, mx1);
        float a0 = __expf(m0v - nm0), a1 = __expf(m1v - nm1);
        m0v = nm0; m1v = nm1;

        float sum0 = 0.f, sum1 = 0.f;
        #pragma unroll
        for (int nt=0;nt<8;nt++) {
            s[nt][0] = __expf(s[nt][0] - m0v);
            s[nt][1] = __expf(s[nt][1] - m0v);
            s[nt][2] = __expf(s[nt][2] - m1v);
            s[nt][3] = __expf(s[nt][3] - m1v);
            sum0 += s[nt][0] + s[nt][1];
            sum1 += s[nt][2] + s[nt][3];
        }
        sum0 += __shfl_xor_sync(0xffffffffu, sum0, 1);
        sum0 += __shfl_xor_sync(0xffffffffu, sum0, 2);
        sum1 += __shfl_xor_sync(0xffffffffu, sum1, 1);
        sum1 += __shfl_xor_sync(0xffffffffu, sum1, 2);
        l0 = l0*a0 + sum0;
        l1 = l1*a1 + sum1;

        // P fragments (layout identity)
        uint32_t pf[4][4];
        #pragma unroll
        for (int kt=0;kt<4;kt++) {
            pf[kt][0] = f22u(s[2*kt  ][0], s[2*kt  ][1]);
            pf[kt][1] = f22u(s[2*kt  ][2], s[2*kt  ][3]);
            pf[kt][2] = f22u(s[2*kt+1][0], s[2*kt+1][1]);
            pf[kt][3] = f22u(s[2*kt+1][2], s[2*kt+1][3]);
        }

        // O rescale + O += P V  (V^T fragments via ldmatrix.trans)
        #pragma unroll
        for (int nt=0;nt<8;nt++) {
            o[nt][0] *= a0; o[nt][1] *= a0;
            o[nt][2] *= a1; o[nt][3] *= a1;
        }
        #pragma unroll
        for (int kt=0;kt<4;kt++) {
            #pragma unroll
            for (int nn=0;nn<4;nn++) {
                uint32_t bf[4];
                ldsm_x4_t(bf, Vb + (kt*16 + lrowT)*(AK_LD*2) + nn*32 + lcolT);
                mma16816(o[2*nn  ], pf[kt], bf);
                mma16816(o[2*nn+1], pf[kt], bf+2);
            }
        }
        __syncthreads();
    }

    // Epilogue
    const int s0 = q0 + rq + r0;
    const int s1 = s0 + 8;
    const float inv0 = (float)q_mask[b*Ss + s0] / l0;
    const float inv1 = (float)q_mask[b*Ss + s1] / l1;
    float* op0 = out + (b*Ss + s0)*DModel + (bh & 15)*Dh;
    float* op1 = out + (b*Ss + s1)*DModel + (bh & 15)*Dh;
    #pragma unroll
    for (int nt=0;nt<8;nt++) {
        int col = nt*8 + qp*2;
        *(float2*)&op0[col] = make_float2(o[nt][0]*inv0, o[nt][1]*inv0);
        *(float2*)&op1[col] = make_float2(o[nt][2]*inv1, o[nt][3]*inv1);
    }
}

// ---------------------------------------------------------------------------
extern "C" void kernel_launch(void* const* d_in, const int* in_sizes, int n_in,
                              void* d_out, int out_size) {
    const float* q  = (const float*)d_in[0];
    const float* k  = (const float*)d_in[1];
    const float* v  = (const float*)d_in[2];
    const int*   vm = (const int*)d_in[3];
    const int*   qm = (const int*)d_in[4];
    const float* Wq = (const float*)d_in[5];
    const float* bq = (const float*)d_in[6];
    const float* Wk = (const float*)d_in[7];
    const float* bk = (const float*)d_in[8];
    const float* Wv = (const float*)d_in[9];
    const float* bv = (const float*)d_in[10];
    float* out = (float*)d_out;

    __half *gxq, *gxk, *gxv, *gwq, *gwk, *gwv;
    cudaGetSymbolAddress((void**)&gxq, g_xq);
    cudaGetSymbolAddress((void**)&gxk, g_xk);
    cudaGetSymbolAddress((void**)&gxv, g_xv);
    cudaGetSymbolAddress((void**)&gwq, g_wq);
    cudaGetSymbolAddress((void**)&gwk, g_wk);
    cudaGetSymbolAddress((void**)&gwv, g_wv);

    cvt_kernel<<<dim3(XN/(256*8), 1, 3), 256>>>(q, k, v, gxq, gxk, gxv);
    cvt_kernel<<<dim3(WN/(256*8), 1, 3), 256>>>(Wq, Wk, Wv, gwq, gwk, gwv);

    const int gsmem = GST*(128*GLDA + 32*GLDB)*2;   // 56832 B
    cudaFuncSetAttribute(gemm_kernel,
                         cudaFuncAttributeMaxDynamicSharedMemorySize, gsmem);
    dim3 gg(Bb*Ss/128, DModel/128, 3);   // (32, 8, 3)
    gemm_kernel<<<gg, 256, gsmem>>>(bq, bk, bv);

    dim3 ag(Ss/128, Bb*Hh);              // (16, 32)
    attn_kernel<<<ag, 256>>>(vm, qm, out);
}

// round 8
// speedup vs baseline: 5.4828x; 1.0466x over previous
#include <cuda_runtime.h>
#include <cuda_fp16.h>
#include <cstdint>

// Problem constants
#define Bb 2
#define Ss 2048
#define DModel 1024
#define Hh 16
#define Dh 64
#define XN (Bb*Ss*DModel)   // 4194304
#define WN (DModel*DModel)  // 1048576

#define LOG2E 1.4426950408889634f
// Mask bias in base-2 domain. fp16-safe (|s-m| stays << 65504) and still
// exact-zero after exp2: unmasked scores are |s| < ~50, so masked entries are
// >= 12700 below the row max -> 2^-12700 == 0 in fp32 and fp16.
#define MBIAS 12800.0f

// fp16 copies of inputs
__device__ __align__(256) __half g_xq[XN], g_xk[XN], g_xv[XN];
__device__ __align__(256) __half g_wq[WN], g_wk[WN], g_wv[WN];
// fp16 projected Q,K,V all in [B,H,S,Dh]  (Q pre-scaled by 0.125*log2e)
__device__ __align__(256) __half g_qh[Bb*Hh*Ss*Dh];
__device__ __align__(256) __half g_kh[Bb*Hh*Ss*Dh];
__device__ __align__(256) __half g_vh[Bb*Hh*Ss*Dh];

// ---------------------------------------------------------------------------
// Helpers
// ---------------------------------------------------------------------------
__device__ __forceinline__ uint32_t smem_u32(const void* p) {
    return (uint32_t)__cvta_generic_to_shared(p);
}
__device__ __forceinline__ void cp16(uint32_t s, const void* g) {
    asm volatile("cp.async.cg.shared.global [%0], [%1], 16;\n" :: "r"(s), "l"(g));
}
#define CP_COMMIT asm volatile("cp.async.commit_group;\n")
template<int N> __device__ __forceinline__ void cp_wait() {
    asm volatile("cp.async.wait_group %0;\n" :: "n"(N));
}
__device__ __forceinline__ void mma16816(float* d, const uint32_t* a, const uint32_t* b) {
    asm volatile(
        "mma.sync.aligned.m16n8k16.row.col.f32.f16.f16.f32 "
        "{%0,%1,%2,%3},{%4,%5,%6,%7},{%8,%9},{%0,%1,%2,%3};\n"
        : "+f"(d[0]), "+f"(d[1]), "+f"(d[2]), "+f"(d[3])
        : "r"(a[0]), "r"(a[1]), "r"(a[2]), "r"(a[3]), "r"(b[0]), "r"(b[1]));
}
__device__ __forceinline__ void ldsm_x4(uint32_t* d, uint32_t a) {
    asm volatile("ldmatrix.sync.aligned.m8n8.x4.shared.b16 {%0,%1,%2,%3},[%4];\n"
        : "=r"(d[0]), "=r"(d[1]), "=r"(d[2]), "=r"(d[3]) : "r"(a));
}
__device__ __forceinline__ void ldsm_x4_t(uint32_t* d, uint32_t a) {
    asm volatile("ldmatrix.sync.aligned.m8n8.x4.trans.shared.b16 {%0,%1,%2,%3},[%4];\n"
        : "=r"(d[0]), "=r"(d[1]), "=r"(d[2]), "=r"(d[3]) : "r"(a));
}
__device__ __forceinline__ void ldsm_x2_t(uint32_t* d, uint32_t a) {
    asm volatile("ldmatrix.sync.aligned.m8n8.x2.trans.shared.b16 {%0,%1},[%2];\n"
        : "=r"(d[0]), "=r"(d[1]) : "r"(a));
}
__device__ __forceinline__ uint32_t f22u(float x, float y) {
    __half2 h = __floats2half2_rn(x, y);
    return *reinterpret_cast<uint32_t*>(&h);
}
__device__ __forceinline__ float ex2f(float x) {
    float y; asm("ex2.approx.ftz.f32 %0, %1;\n" : "=f"(y) : "f"(x)); return y;
}
__device__ __forceinline__ uint32_t h2exp2(uint32_t x) {
    uint32_t y; asm("ex2.approx.f16x2 %0, %1;\n" : "=r"(y) : "r"(x)); return y;
}

// ---------------------------------------------------------------------------
// fp32 -> fp16 conversion (8 elems/thread), z selects tensor
// ---------------------------------------------------------------------------
__global__ __launch_bounds__(256) void cvt_kernel(
    const float* __restrict__ a, const float* __restrict__ b, const float* __restrict__ c,
    __half* __restrict__ oa, __half* __restrict__ ob, __half* __restrict__ oc)
{
    const int z = blockIdx.z;
    const float* in = (z==0) ? a : (z==1) ? b : c;
    __half* outp    = (z==0) ? oa : (z==1) ? ob : oc;
    int i = (blockIdx.x * 256 + threadIdx.x) * 8;
    float4 v0 = *(const float4*)&in[i];
    float4 v1 = *(const float4*)&in[i+4];
    uint4 w;
    w.x = f22u(v0.x, v0.y); w.y = f22u(v0.z, v0.w);
    w.z = f22u(v1.x, v1.y); w.w = f22u(v1.z, v1.w);
    *(uint4*)&outp[i] = w;
}

// ---------------------------------------------------------------------------
// QKV projection GEMM (fp16 in/out, fp32 acc): Y = X @ W + bias
// Block 128m x 128n, k-tile 32, 3-stage cp.async, 8 warps (4m x 2n), warp 32x64.
// z=0 -> g_qh (scaled 0.125*log2e), z=1 -> g_kh, z=2 -> g_vh. All [B,H,S,Dh].
// ---------------------------------------------------------------------------
#define GLDA 40    // halves per A smem row (32+8)
#define GLDB 136   // halves per B smem row (128+8)
#define GST 3

__global__ __launch_bounds__(256) void gemm_kernel(
    const float* __restrict__ bq, const float* __restrict__ bk, const float* __restrict__ bv)
{
    extern __shared__ __align__(16) __half gsm[];
    __half* sA = gsm;                      // GST x 128 x GLDA
    __half* sB = gsm + GST*128*GLDA;       // GST x 32 x GLDB

    const int z = blockIdx.z;
    const __half* X = (z==0) ? g_xq : (z==1) ? g_xk : g_xv;
    const __half* W = (z==0) ? g_wq : (z==1) ? g_wk : g_wv;
    const float* bias = (z==0) ? bq : (z==1) ? bk : bv;
    __half* G = (z==0) ? g_qh : (z==1) ? g_kh : g_vh;
    const float scale = (z==0) ? (0.125f*LOG2E) : 1.0f;

    const int tid = threadIdx.x;
    const int warp = tid >> 5, lane = tid & 31;
    const int wm = warp >> 1, wn = warp & 1;
    const int r0 = lane >> 2, qp = lane & 3;
    const int m0 = blockIdx.x * 128, n0 = blockIdx.y * 128;

    float acc[2][8][4];
    #pragma unroll
    for (int mi=0;mi<2;mi++)
        #pragma unroll
        for (int ni=0;ni<8;ni++)
            #pragma unroll
            for (int c=0;c<4;c++) acc[mi][ni][c] = 0.f;

    const uint32_t sAu = smem_u32(sA), sBu = smem_u32(sB);
    const int lrow = (lane & 7) + (lane & 8);
    const int lcol = ((lane & 16) >> 4) * 16;

    auto issue = [&](int st, int kt) {
        #pragma unroll
        for (int p=0;p<2;p++) {            // A: 128x32 halves = 512 x 16B
            int ch = tid + p*256;
            int row = ch >> 2, co = ch & 3;
            cp16(sAu + (st*128 + row)*(GLDA*2) + co*16,
                 X + (m0+row)*DModel + kt*32 + co*8);
        }
        #pragma unroll
        for (int p=0;p<2;p++) {            // B: 32x128 halves = 512 x 16B
            int ch = tid + p*256;
            int row = ch >> 4, co = ch & 15;
            cp16(sBu + (st*32 + row)*(GLDB*2) + co*16,
                 W + (kt*32+row)*DModel + n0 + co*8);
        }
    };

    issue(0, 0); CP_COMMIT;
    issue(1, 1); CP_COMMIT;

    for (int kt = 0; kt < 32; kt++) {
        if (kt == 31) cp_wait<0>(); else cp_wait<1>();
        __syncthreads();
        if (kt < 30) { issue((kt+2)%GST, kt+2); CP_COMMIT; }

        const int st = kt % GST;
        const uint32_t Abase = sAu + st*128*(GLDA*2);
        const uint32_t Bbase = sBu + st*32*(GLDB*2);

        #pragma unroll
        for (int ks = 0; ks < 32; ks += 16) {
            uint32_t af[2][4];
            #pragma unroll
            for (int mi=0;mi<2;mi++)
                ldsm_x4(af[mi], Abase + (wm*32 + mi*16 + lrow)*(GLDA*2) + ks*2 + lcol);
            #pragma unroll
            for (int nn=0;nn<4;nn++) {
                uint32_t bf[4];
                ldsm_x4_t(bf, Bbase + (ks + lrow)*(GLDB*2) + (wn*64 + nn*16)*2 + lcol);
                #pragma unroll
                for (int mi=0;mi<2;mi++) {
                    mma16816(acc[mi][2*nn  ], af[mi], bf);
                    mma16816(acc[mi][2*nn+1], af[mi], bf+2);
                }
            }
        }
        __syncthreads();
    }

    // Epilogue: bias + scale, fp16 store to [B,H,S,Dh]
    const int b = m0 >> 11;
    const int h0 = (n0 >> 6) + wn;
    const int sbase = (m0 & (Ss-1)) + wm*32;
    __half* Gb = G + (b*Hh + h0)*Ss*Dh;
    #pragma unroll
    for (int mi=0;mi<2;mi++) {
        int sr = sbase + mi*16 + r0;
        #pragma unroll
        for (int ni=0;ni<8;ni++) {
            int col = ni*8 + qp*2;
            float2 bb = *(const float2*)&bias[n0 + wn*64 + col];
            *(__half2*)&Gb[ sr   *Dh + col] =
                __floats2half2_rn((acc[mi][ni][0]+bb.x)*scale, (acc[mi][ni][1]+bb.y)*scale);
            *(__half2*)&Gb[(sr+8)*Dh + col] =
                __floats2half2_rn((acc[mi][ni][2]+bb.x)*scale, (acc[mi][ni][3]+bb.y)*scale);
        }
    }
}

// ---------------------------------------------------------------------------
// Flash attention: Q-tile 128 (8 warps x 16 rows), KV-tile 64, fp16 mma,
// 3-stage cp.async pipeline, ONE __syncthreads per tile, base-2 softmax with
// f16x2 ex2 (fp16-safe mask bias), row-sum via ones-column in V (broadcast
// across the quad at the end), warp-uniform rescale skip.
// ---------------------------------------------------------------------------
#define AK_LD 72                 // halves per smem row (64 data + 8 pad)
#define AST (64*AK_LD)           // halves per stage per tensor
#define ASMEM (6*AST*2 + 3*64*4) // bytes: 3xK + 3xV + 3x64 bias floats

__global__ __launch_bounds__(256,2) void attn_kernel(
    const int* __restrict__ v_mask, const int* __restrict__ q_mask,
    float* __restrict__ out)
{
    extern __shared__ __align__(16) __half asmem[];
    __half* sK = asmem;                 // 3 x 64 x AK_LD
    __half* sV = asmem + 3*AST;         // 3 x 64 x AK_LD
    float* sBias = (float*)(asmem + 6*AST);   // 3 x 64

    const int tid = threadIdx.x;
    const int warp = tid >> 5, lane = tid & 31;
    const int r0 = lane >> 2, qp = lane & 3;
    const int bh = blockIdx.y, b = bh >> 4;
    const int q0 = blockIdx.x * 128;
    const int rq = warp * 16;

    const __half* gQ = g_qh + (bh*Ss + q0 + rq)*Dh;
    const __half* gK = g_kh + bh*Ss*Dh;
    const __half* gV = g_vh + bh*Ss*Dh;

    // Persistent Q fragments
    uint32_t qf[4][4];
    #pragma unroll
    for (int kt=0;kt<4;kt++) {
        int k0 = kt*16 + qp*2;
        qf[kt][0] = *(const uint32_t*)&gQ[(r0  )*Dh + k0];
        qf[kt][1] = *(const uint32_t*)&gQ[(r0+8)*Dh + k0];
        qf[kt][2] = *(const uint32_t*)&gQ[(r0  )*Dh + k0+8];
        qf[kt][3] = *(const uint32_t*)&gQ[(r0+8)*Dh + k0+8];
    }

    float o[8][4];
    #pragma unroll
    for (int nt=0;nt<8;nt++)
        #pragma unroll
        for (int c=0;c<4;c++) o[nt][c] = 0.f;
    float ol[4] = {0.f, 0.f, 0.f, 0.f};     // ones-col: l in ol[0]/ol[2] of qp==0
    float m0v = -1e30f, m1v = -1e30f;

    const uint32_t skb = smem_u32(sK), svb = smem_u32(sV);
    const int lrowT = (lane & 7) + (lane & 8);
    const int lcolT = ((lane & 16) >> 4) * 16;
    const int lrowK = (lane & 7) + ((lane & 16) >> 1);
    const int lcolK = (lane & 8) << 1;

    auto issue = [&](int st, int kv0) {
        #pragma unroll
        for (int p=0;p<2;p++) {
            int ch = tid + p*256;
            int row = ch >> 3, co = ch & 7;
            cp16(skb + st*(AST*2) + row*(AK_LD*2) + co*16, gK + (kv0+row)*Dh + co*8);
            cp16(svb + st*(AST*2) + row*(AK_LD*2) + co*16, gV + (kv0+row)*Dh + co*8);
        }
    };

    issue(0, 0); CP_COMMIT;
    issue(1, 64); CP_COMMIT;

    // Init V pad columns (64..71): col64 = 1.0, rest 0. cp.async never touches
    // these bytes, so they persist across all stages/tiles.
    for (int i = tid; i < 3*64*4; i += 256) {
        int stage = i >> 8;
        int rem = i & 255;
        int row = rem >> 2, cp = rem & 3;
        *(__half2*)&sV[stage*AST + row*AK_LD + 64 + cp*2] =
            (cp==0) ? __floats2half2_rn(1.f, 0.f) : __floats2half2_rn(0.f, 0.f);
    }

    int vreg = 0;
    if (tid < 64) vreg = v_mask[b*Ss + tid];

    for (int t = 0; t < 32; t++) {
        const int st = t % 3;
        const int kv0 = t * 64;
        if (tid < 64) {
            sBias[st*64 + tid] = ((float)vreg - 1.0f) * MBIAS;
            if (t < 31) vreg = v_mask[b*Ss + kv0 + 64 + tid];
        }
        if (t < 30) cp_wait<1>(); else cp_wait<0>();
        __syncthreads();
        if (t + 2 < 32) { issue((t+2)%3, kv0 + 128); CP_COMMIT; }

        const uint32_t Kb = skb + st*(AST*2);
        const uint32_t Vb = svb + st*(AST*2);
        const float* bias = sBias + st*64;

        // S = Q K^T
        float s[8][4];
        #pragma unroll
        for (int nt=0;nt<8;nt++)
            #pragma unroll
            for (int c=0;c<4;c++) s[nt][c] = 0.f;

        #pragma unroll
        for (int kt=0;kt<4;kt++) {
            #pragma unroll
            for (int nn=0;nn<4;nn++) {
                uint32_t bf[4];
                ldsm_x4(bf, Kb + (nn*16 + lrowK)*(AK_LD*2) + kt*32 + lcolK);
                mma16816(s[2*nn  ], qf[kt], bf);
                mma16816(s[2*nn+1], qf[kt], bf+2);
            }
        }

        // bias + row max
        float mx0 = -1e30f, mx1 = -1e30f;
        #pragma unroll
        for (int nt=0;nt<8;nt++) {
            float2 bb = *(const float2*)&bias[nt*8 + qp*2];
            s[nt][0] += bb.x; s[nt][1] += bb.y;
            s[nt][2] += bb.x; s[nt][3] += bb.y;
            mx0 = fmaxf(mx0, fmaxf(s[nt][0], s[nt][1]));
            mx1 = fmaxf(mx1, fmaxf(s[nt][2], s[nt][3]));
        }
        mx0 = fmaxf(mx0, __shfl_xor_sync(0xffffffffu, mx0, 1));
        mx0 = fmaxf(mx0, __shfl_xor_sync(0xffffffffu, mx0, 2));
        mx1 = fmaxf(mx1, __shfl_xor_sync(0xffffffffu, mx1, 1));
        mx1 = fmaxf(mx1, __shfl_xor_sync(0xffffffffu, mx1, 2));

        const float nm0 = fmaxf(m0v, mx0), nm1 = fmaxf(m1v, mx1);
        const bool same = (nm0 == m0v) && (nm1 == m1v);
        if (!__all_sync(0xffffffffu, same)) {
            const float a0 = ex2f(m0v - nm0), a1 = ex2f(m1v - nm1);
            #pragma unroll
            for (int nt=0;nt<8;nt++) {
                o[nt][0] *= a0; o[nt][1] *= a0;
                o[nt][2] *= a1; o[nt][3] *= a1;
            }
            ol[0] *= a0; ol[2] *= a1;
        }
        m0v = nm0; m1v = nm1;

        // P = 2^(s-m) in packed fp16 (f16x2 MUFU), directly in A-frag layout.
        // s-m is in [-MBIAS-100, 0] -> finite in fp16, exp2 underflows to 0.
        uint32_t pf[4][4];
        #pragma unroll
        for (int kt=0;kt<4;kt++) {
            pf[kt][0] = h2exp2(f22u(s[2*kt  ][0]-m0v, s[2*kt  ][1]-m0v));
            pf[kt][1] = h2exp2(f22u(s[2*kt  ][2]-m1v, s[2*kt  ][3]-m1v));
            pf[kt][2] = h2exp2(f22u(s[2*kt+1][0]-m0v, s[2*kt+1][1]-m0v));
            pf[kt][3] = h2exp2(f22u(s[2*kt+1][2]-m1v, s[2*kt+1][3]-m1v));
        }

        // O += P V ; l accumulates via ones-column (cols 64..71 of V)
        #pragma unroll
        for (int kt=0;kt<4;kt++) {
            #pragma unroll
            for (int nn=0;nn<4;nn++) {
                uint32_t bf[4];
                ldsm_x4_t(bf, Vb + (kt*16 + lrowT)*(AK_LD*2) + nn*32 + lcolT);
                mma16816(o[2*nn  ], pf[kt], bf);
                mma16816(o[2*nn+1], pf[kt], bf+2);
            }
            uint32_t bl[2];
            ldsm_x2_t(bl, Vb + (kt*16 + lrowT)*(AK_LD*2) + 64*2);
            mma16816(ol, pf[kt], bl);
        }
    }

    // Row sums live only in the qp==0 lane of each quad (ones are in V pad
    // col 64, which maps to accumulator cols 0,1 of the pad n-tile; col 0 is
    // the ones column). Broadcast from lane (r0*4) = (lane & 28).
    const float l0 = __shfl_sync(0xffffffffu, ol[0], lane & 28);
    const float l1 = __shfl_sync(0xffffffffu, ol[2], lane & 28);

    // Epilogue: O / l, q_mask, write [B,S,H*Dh] fp32
    const int s0 = q0 + rq + r0;
    const int s1 = s0 + 8;
    const float inv0 = (float)q_mask[b*Ss + s0] / l0;
    const float inv1 = (float)q_mask[b*Ss + s1] / l1;
    float* op0 = out + (b*Ss + s0)*DModel + (bh & 15)*Dh;
    float* op1 = out + (b*Ss + s1)*DModel + (bh & 15)*Dh;
    #pragma unroll
    for (int nt=0;nt<8;nt++) {
        int col = nt*8 + qp*2;
        *(float2*)&op0[col] = make_float2(o[nt][0]*inv0, o[nt][1]*inv0);
        *(float2*)&op1[col] = make_float2(o[nt][2]*inv1, o[nt][3]*inv1);
    }
}

// ---------------------------------------------------------------------------
extern "C" void kernel_launch(void* const* d_in, const int* in_sizes, int n_in,
                              void* d_out, int out_size) {
    const float* q  = (const float*)d_in[0];
    const float* k  = (const float*)d_in[1];
    const float* v  = (const float*)d_in[2];
    const int*   vm = (const int*)d_in[3];
    const int*   qm = (const int*)d_in[4];
    const float* Wq = (const float*)d_in[5];
    const float* bq = (const float*)d_in[6];
    const float* Wk = (const float*)d_in[7];
    const float* bk = (const float*)d_in[8];
    const float* Wv = (const float*)d_in[9];
    const float* bv = (const float*)d_in[10];
    float* out = (float*)d_out;

    __half *gxq, *gxk, *gxv, *gwq, *gwk, *gwv;
    cudaGetSymbolAddress((void**)&gxq, g_xq);
    cudaGetSymbolAddress((void**)&gxk, g_xk);
    cudaGetSymbolAddress((void**)&gxv, g_xv);
    cudaGetSymbolAddress((void**)&gwq, g_wq);
    cudaGetSymbolAddress((void**)&gwk, g_wk);
    cudaGetSymbolAddress((void**)&gwv, g_wv);

    cvt_kernel<<<dim3(XN/(256*8), 1, 3), 256>>>(q, k, v, gxq, gxk, gxv);
    cvt_kernel<<<dim3(WN/(256*8), 1, 3), 256>>>(Wq, Wk, Wv, gwq, gwk, gwv);

    const int gsmem = GST*(128*GLDA + 32*GLDB)*2;   // 56832 B
    cudaFuncSetAttribute(gemm_kernel,
                         cudaFuncAttributeMaxDynamicSharedMemorySize, gsmem);
    dim3 gg(Bb*Ss/128, DModel/128, 3);   // (32, 8, 3)
    gemm_kernel<<<gg, 256, gsmem>>>(bq, bk, bv);

    cudaFuncSetAttribute(attn_kernel,
                         cudaFuncAttributeMaxDynamicSharedMemorySize, ASMEM);
    dim3 ag(Ss/128, Bb*Hh);              // (16, 32)
    attn_kernel<<<ag, 256, ASMEM>>>(vm, qm, out);
}

// round 9
// speedup vs baseline: 5.7460x; 1.0480x over previous
#include <cuda_runtime.h>
#include <cuda_fp16.h>
#include <cstdint>

// Problem constants
#define Bb 2
#define Ss 2048
#define DModel 1024
#define Hh 16
#define Dh 64
#define XN (Bb*Ss*DModel)   // 4194304
#define WN (DModel*DModel)  // 1048576

#define LOG2E 1.4426950408889634f
// Mask bias in base-2 domain. fp16-safe and exact-zero after exp2.
#define MBIAS 12800.0f

// fp16 copies of inputs
__device__ __align__(256) __half g_xq[XN], g_xk[XN], g_xv[XN];
__device__ __align__(256) __half g_wq[WN], g_wk[WN], g_wv[WN];
// fp16 projected Q,K,V all in [B,H,S,Dh]  (Q pre-scaled by 0.125*log2e)
__device__ __align__(256) __half g_qh[Bb*Hh*Ss*Dh];
__device__ __align__(256) __half g_kh[Bb*Hh*Ss*Dh];
__device__ __align__(256) __half g_vh[Bb*Hh*Ss*Dh];

// ---------------------------------------------------------------------------
// Helpers
// ---------------------------------------------------------------------------
__device__ __forceinline__ uint32_t smem_u32(const void* p) {
    return (uint32_t)__cvta_generic_to_shared(p);
}
__device__ __forceinline__ void cp16(uint32_t s, const void* g) {
    asm volatile("cp.async.cg.shared.global [%0], [%1], 16;\n" :: "r"(s), "l"(g));
}
#define CP_COMMIT asm volatile("cp.async.commit_group;\n")
template<int N> __device__ __forceinline__ void cp_wait() {
    asm volatile("cp.async.wait_group %0;\n" :: "n"(N));
}
__device__ __forceinline__ void mma16816(float* d, const uint32_t* a, const uint32_t* b) {
    asm volatile(
        "mma.sync.aligned.m16n8k16.row.col.f32.f16.f16.f32 "
        "{%0,%1,%2,%3},{%4,%5,%6,%7},{%8,%9},{%0,%1,%2,%3};\n"
        : "+f"(d[0]), "+f"(d[1]), "+f"(d[2]), "+f"(d[3])
        : "r"(a[0]), "r"(a[1]), "r"(a[2]), "r"(a[3]), "r"(b[0]), "r"(b[1]));
}
__device__ __forceinline__ void ldsm_x4(uint32_t* d, uint32_t a) {
    asm volatile("ldmatrix.sync.aligned.m8n8.x4.shared.b16 {%0,%1,%2,%3},[%4];\n"
        : "=r"(d[0]), "=r"(d[1]), "=r"(d[2]), "=r"(d[3]) : "r"(a));
}
__device__ __forceinline__ void ldsm_x4_t(uint32_t* d, uint32_t a) {
    asm volatile("ldmatrix.sync.aligned.m8n8.x4.trans.shared.b16 {%0,%1,%2,%3},[%4];\n"
        : "=r"(d[0]), "=r"(d[1]), "=r"(d[2]), "=r"(d[3]) : "r"(a));
}
__device__ __forceinline__ void ldsm_x2_t(uint32_t* d, uint32_t a) {
    asm volatile("ldmatrix.sync.aligned.m8n8.x2.trans.shared.b16 {%0,%1},[%2];\n"
        : "=r"(d[0]), "=r"(d[1]) : "r"(a));
}
__device__ __forceinline__ uint32_t f22u(float x, float y) {
    __half2 h = __floats2half2_rn(x, y);
    return *reinterpret_cast<uint32_t*>(&h);
}
__device__ __forceinline__ float ex2f(float x) {
    float y; asm("ex2.approx.ftz.f32 %0, %1;\n" : "=f"(y) : "f"(x)); return y;
}
__device__ __forceinline__ uint32_t h2exp2(uint32_t x) {
    uint32_t y; asm("ex2.approx.f16x2 %0, %1;\n" : "=r"(y) : "r"(x)); return y;
}

// ---------------------------------------------------------------------------
// fp32 -> fp16 conversion (8 elems/thread), z selects tensor
// ---------------------------------------------------------------------------
__global__ __launch_bounds__(256) void cvt_kernel(
    const float* __restrict__ a, const float* __restrict__ b, const float* __restrict__ c,
    __half* __restrict__ oa, __half* __restrict__ ob, __half* __restrict__ oc)
{
    const int z = blockIdx.z;
    const float* in = (z==0) ? a : (z==1) ? b : c;
    __half* outp    = (z==0) ? oa : (z==1) ? ob : oc;
    int i = (blockIdx.x * 256 + threadIdx.x) * 8;
    float4 v0 = *(const float4*)&in[i];
    float4 v1 = *(const float4*)&in[i+4];
    uint4 w;
    w.x = f22u(v0.x, v0.y); w.y = f22u(v0.z, v0.w);
    w.z = f22u(v1.x, v1.y); w.w = f22u(v1.z, v1.w);
    *(uint4*)&outp[i] = w;
}

// ---------------------------------------------------------------------------
// QKV projection GEMM (fp16 in/out, fp32 acc): Y = X @ W + bias
// Block 128m x 128n, k-tile 32, 3-stage cp.async, 8 warps (4m x 2n), warp 32x64.
// z=0 -> g_qh (scaled 0.125*log2e), z=1 -> g_kh, z=2 -> g_vh. All [B,H,S,Dh].
// ---------------------------------------------------------------------------
#define GLDA 40    // halves per A smem row (32+8)
#define GLDB 136   // halves per B smem row (128+8)
#define GST 3

__global__ __launch_bounds__(256) void gemm_kernel(
    const float* __restrict__ bq, const float* __restrict__ bk, const float* __restrict__ bv)
{
    extern __shared__ __align__(16) __half gsm[];
    __half* sA = gsm;                      // GST x 128 x GLDA
    __half* sB = gsm + GST*128*GLDA;       // GST x 32 x GLDB

    const int z = blockIdx.z;
    const __half* X = (z==0) ? g_xq : (z==1) ? g_xk : g_xv;
    const __half* W = (z==0) ? g_wq : (z==1) ? g_wk : g_wv;
    const float* bias = (z==0) ? bq : (z==1) ? bk : bv;
    __half* G = (z==0) ? g_qh : (z==1) ? g_kh : g_vh;
    const float scale = (z==0) ? (0.125f*LOG2E) : 1.0f;

    const int tid = threadIdx.x;
    const int warp = tid >> 5, lane = tid & 31;
    const int wm = warp >> 1, wn = warp & 1;
    const int r0 = lane >> 2, qp = lane & 3;
    const int m0 = blockIdx.x * 128, n0 = blockIdx.y * 128;

    float acc[2][8][4];
    #pragma unroll
    for (int mi=0;mi<2;mi++)
        #pragma unroll
        for (int ni=0;ni<8;ni++)
            #pragma unroll
            for (int c=0;c<4;c++) acc[mi][ni][c] = 0.f;

    const uint32_t sAu = smem_u32(sA), sBu = smem_u32(sB);
    const int lrow = (lane & 7) + (lane & 8);
    const int lcol = ((lane & 16) >> 4) * 16;

    auto issue = [&](int st, int kt) {
        #pragma unroll
        for (int p=0;p<2;p++) {            // A: 128x32 halves = 512 x 16B
            int ch = tid + p*256;
            int row = ch >> 2, co = ch & 3;
            cp16(sAu + (st*128 + row)*(GLDA*2) + co*16,
                 X + (m0+row)*DModel + kt*32 + co*8);
        }
        #pragma unroll
        for (int p=0;p<2;p++) {            // B: 32x128 halves = 512 x 16B
            int ch = tid + p*256;
            int row = ch >> 4, co = ch & 15;
            cp16(sBu + (st*32 + row)*(GLDB*2) + co*16,
                 W + (kt*32+row)*DModel + n0 + co*8);
        }
    };

    issue(0, 0); CP_COMMIT;
    issue(1, 1); CP_COMMIT;

    for (int kt = 0; kt < 32; kt++) {
        if (kt == 31) cp_wait<0>(); else cp_wait<1>();
        __syncthreads();
        if (kt < 30) { issue((kt+2)%GST, kt+2); CP_COMMIT; }

        const int st = kt % GST;
        const uint32_t Abase = sAu + st*128*(GLDA*2);
        const uint32_t Bbase = sBu + st*32*(GLDB*2);

        #pragma unroll
        for (int ks = 0; ks < 32; ks += 16) {
            uint32_t af[2][4];
            #pragma unroll
            for (int mi=0;mi<2;mi++)
                ldsm_x4(af[mi], Abase + (wm*32 + mi*16 + lrow)*(GLDA*2) + ks*2 + lcol);
            #pragma unroll
            for (int nn=0;nn<4;nn++) {
                uint32_t bf[4];
                ldsm_x4_t(bf, Bbase + (ks + lrow)*(GLDB*2) + (wn*64 + nn*16)*2 + lcol);
                #pragma unroll
                for (int mi=0;mi<2;mi++) {
                    mma16816(acc[mi][2*nn  ], af[mi], bf);
                    mma16816(acc[mi][2*nn+1], af[mi], bf+2);
                }
            }
        }
        __syncthreads();
    }

    // Epilogue: bias + scale, fp16 store to [B,H,S,Dh]
    const int b = m0 >> 11;
    const int h0 = (n0 >> 6) + wn;
    const int sbase = (m0 & (Ss-1)) + wm*32;
    __half* Gb = G + (b*Hh + h0)*Ss*Dh;
    #pragma unroll
    for (int mi=0;mi<2;mi++) {
        int sr = sbase + mi*16 + r0;
        #pragma unroll
        for (int ni=0;ni<8;ni++) {
            int col = ni*8 + qp*2;
            float2 bb = *(const float2*)&bias[n0 + wn*64 + col];
            *(__half2*)&Gb[ sr   *Dh + col] =
                __floats2half2_rn((acc[mi][ni][0]+bb.x)*scale, (acc[mi][ni][1]+bb.y)*scale);
            *(__half2*)&Gb[(sr+8)*Dh + col] =
                __floats2half2_rn((acc[mi][ni][2]+bb.x)*scale, (acc[mi][ni][3]+bb.y)*scale);
        }
    }
}

// ---------------------------------------------------------------------------
// Flash attention: 4-warp CTA (128 threads), Q-tile 64, KV-tile 64, fp16 mma,
// 3-stage cp.async pipeline, one __syncthreads per tile, base-2 softmax with
// f16x2 ex2, row-sum via ones-column in V (quad-broadcast at end),
// warp-uniform rescale skip. Small CTAs -> 4 independent CTAs per SM with
//独立 barriers, so softmax of one CTA overlaps MMA of another on each SMSP.
// ---------------------------------------------------------------------------
#define AK_LD 72                 // halves per smem row (64 data + 8 pad)
#define AST (64*AK_LD)           // halves per stage per tensor
#define ASMEM (6*AST*2 + 3*64*4) // bytes: 3xK + 3xV + 3x64 bias floats = 56064

__global__ __launch_bounds__(128,4) void attn_kernel(
    const int* __restrict__ v_mask, const int* __restrict__ q_mask,
    float* __restrict__ out)
{
    extern __shared__ __align__(16) __half asmem[];
    __half* sK = asmem;                 // 3 x 64 x AK_LD
    __half* sV = asmem + 3*AST;         // 3 x 64 x AK_LD
    float* sBias = (float*)(asmem + 6*AST);   // 3 x 64

    const int tid = threadIdx.x;
    const int warp = tid >> 5, lane = tid & 31;
    const int r0 = lane >> 2, qp = lane & 3;
    const int bh = blockIdx.y, b = bh >> 4;
    const int q0 = blockIdx.x * 64;
    const int rq = warp * 16;

    const __half* gQ = g_qh + (bh*Ss + q0 + rq)*Dh;
    const __half* gK = g_kh + bh*Ss*Dh;
    const __half* gV = g_vh + bh*Ss*Dh;

    // Persistent Q fragments
    uint32_t qf[4][4];
    #pragma unroll
    for (int kt=0;kt<4;kt++) {
        int k0 = kt*16 + qp*2;
        qf[kt][0] = *(const uint32_t*)&gQ[(r0  )*Dh + k0];
        qf[kt][1] = *(const uint32_t*)&gQ[(r0+8)*Dh + k0];
        qf[kt][2] = *(const uint32_t*)&gQ[(r0  )*Dh + k0+8];
        qf[kt][3] = *(const uint32_t*)&gQ[(r0+8)*Dh + k0+8];
    }

    float o[8][4];
    #pragma unroll
    for (int nt=0;nt<8;nt++)
        #pragma unroll
        for (int c=0;c<4;c++) o[nt][c] = 0.f;
    float ol[4] = {0.f, 0.f, 0.f, 0.f};     // ones-col: l in ol[0]/ol[2] of qp==0
    float m0v = -1e30f, m1v = -1e30f;

    const uint32_t skb = smem_u32(sK), svb = smem_u32(sV);
    const int lrowT = (lane & 7) + (lane & 8);
    const int lcolT = ((lane & 16) >> 4) * 16;
    const int lrowK = (lane & 7) + ((lane & 16) >> 1);
    const int lcolK = (lane & 8) << 1;

    auto issue = [&](int st, int kv0) {
        #pragma unroll
        for (int p=0;p<4;p++) {          // 512 x 16B each for K and V, 128 thr
            int ch = tid + p*128;
            int row = ch >> 3, co = ch & 7;
            cp16(skb + st*(AST*2) + row*(AK_LD*2) + co*16, gK + (kv0+row)*Dh + co*8);
            cp16(svb + st*(AST*2) + row*(AK_LD*2) + co*16, gV + (kv0+row)*Dh + co*8);
        }
    };

    issue(0, 0); CP_COMMIT;
    issue(1, 64); CP_COMMIT;

    // Init V pad columns (64..71): col64 = 1.0, rest 0. cp.async never touches
    // these bytes, so they persist across all stages/tiles.
    for (int i = tid; i < 3*64*4; i += 128) {
        int stage = i >> 8;
        int rem = i & 255;
        int row = rem >> 2, cp = rem & 3;
        *(__half2*)&sV[stage*AST + row*AK_LD + 64 + cp*2] =
            (cp==0) ? __floats2half2_rn(1.f, 0.f) : __floats2half2_rn(0.f, 0.f);
    }

    int vreg = 0;
    if (tid < 64) vreg = v_mask[b*Ss + tid];

    for (int t = 0; t < 32; t++) {
        const int st = t % 3;
        const int kv0 = t * 64;
        if (tid < 64) {
            sBias[st*64 + tid] = ((float)vreg - 1.0f) * MBIAS;
            if (t < 31) vreg = v_mask[b*Ss + kv0 + 64 + tid];
        }
        if (t < 30) cp_wait<1>(); else cp_wait<0>();
        __syncthreads();
        if (t + 2 < 32) { issue((t+2)%3, kv0 + 128); CP_COMMIT; }

        const uint32_t Kb = skb + st*(AST*2);
        const uint32_t Vb = svb + st*(AST*2);
        const float* bias = sBias + st*64;

        // S = Q K^T
        float s[8][4];
        #pragma unroll
        for (int nt=0;nt<8;nt++)
            #pragma unroll
            for (int c=0;c<4;c++) s[nt][c] = 0.f;

        #pragma unroll
        for (int kt=0;kt<4;kt++) {
            #pragma unroll
            for (int nn=0;nn<4;nn++) {
                uint32_t bf[4];
                ldsm_x4(bf, Kb + (nn*16 + lrowK)*(AK_LD*2) + kt*32 + lcolK);
                mma16816(s[2*nn  ], qf[kt], bf);
                mma16816(s[2*nn+1], qf[kt], bf+2);
            }
        }

        // bias + row max
        float mx0 = -1e30f, mx1 = -1e30f;
        #pragma unroll
        for (int nt=0;nt<8;nt++) {
            float2 bb = *(const float2*)&bias[nt*8 + qp*2];
            s[nt][0] += bb.x; s[nt][1] += bb.y;
            s[nt][2] += bb.x; s[nt][3] += bb.y;
            mx0 = fmaxf(mx0, fmaxf(s[nt][0], s[nt][1]));
            mx1 = fmaxf(mx1, fmaxf(s[nt][2], s[nt][3]));
        }
        mx0 = fmaxf(mx0, __shfl_xor_sync(0xffffffffu, mx0, 1));
        mx0 = fmaxf(mx0, __shfl_xor_sync(0xffffffffu, mx0, 2));
        mx1 = fmaxf(mx1, __shfl_xor_sync(0xffffffffu, mx1, 1));
        mx1 = fmaxf(mx1, __shfl_xor_sync(0xffffffffu, mx1, 2));

        const float nm0 = fmaxf(m0v, mx0), nm1 = fmaxf(m1v, mx1);
        const bool same = (nm0 == m0v) && (nm1 == m1v);
        if (!__all_sync(0xffffffffu, same)) {
            const float a0 = ex2f(m0v - nm0), a1 = ex2f(m1v - nm1);
            #pragma unroll
            for (int nt=0;nt<8;nt++) {
                o[nt][0] *= a0; o[nt][1] *= a0;
                o[nt][2] *= a1; o[nt][3] *= a1;
            }
            ol[0] *= a0; ol[2] *= a1;
        }
        m0v = nm0; m1v = nm1;

        // P = 2^(s-m) in packed fp16 (f16x2 MUFU), directly in A-frag layout.
        uint32_t pf[4][4];
        #pragma unroll
        for (int kt=0;kt<4;kt++) {
            pf[kt][0] = h2exp2(f22u(s[2*kt  ][0]-m0v, s[2*kt  ][1]-m0v));
            pf[kt][1] = h2exp2(f22u(s[2*kt  ][2]-m1v, s[2*kt  ][3]-m1v));
            pf[kt][2] = h2exp2(f22u(s[2*kt+1][0]-m0v, s[2*kt+1][1]-m0v));
            pf[kt][3] = h2exp2(f22u(s[2*kt+1][2]-m1v, s[2*kt+1][3]-m1v));
        }

        // O += P V ; l accumulates via ones-column (cols 64..71 of V)
        #pragma unroll
        for (int kt=0;kt<4;kt++) {
            #pragma unroll
            for (int nn=0;nn<4;nn++) {
                uint32_t bf[4];
                ldsm_x4_t(bf, Vb + (kt*16 + lrowT)*(AK_LD*2) + nn*32 + lcolT);
                mma16816(o[2*nn  ], pf[kt], bf);
                mma16816(o[2*nn+1], pf[kt], bf+2);
            }
            uint32_t bl[2];
            ldsm_x2_t(bl, Vb + (kt*16 + lrowT)*(AK_LD*2) + 64*2);
            mma16816(ol, pf[kt], bl);
        }
    }

    // Row sums live only in the qp==0 lane of each quad; broadcast.
    const float l0 = __shfl_sync(0xffffffffu, ol[0], lane & 28);
    const float l1 = __shfl_sync(0xffffffffu, ol[2], lane & 28);

    // Epilogue: O / l, q_mask, write [B,S,H*Dh] fp32
    const int s0 = q0 + rq + r0;
    const int s1 = s0 + 8;
    const float inv0 = (float)q_mask[b*Ss + s0] / l0;
    const float inv1 = (float)q_mask[b*Ss + s1] / l1;
    float* op0 = out + (b*Ss + s0)*DModel + (bh & 15)*Dh;
    float* op1 = out + (b*Ss + s1)*DModel + (bh & 15)*Dh;
    #pragma unroll
    for (int nt=0;nt<8;nt++) {
        int col = nt*8 + qp*2;
        *(float2*)&op0[col] = make_float2(o[nt][0]*inv0, o[nt][1]*inv0);
        *(float2*)&op1[col] = make_float2(o[nt][2]*inv1, o[nt][3]*inv1);
    }
}

// ---------------------------------------------------------------------------
extern "C" void kernel_launch(void* const* d_in, const int* in_sizes, int n_in,
                              void* d_out, int out_size) {
    const float* q  = (const float*)d_in[0];
    const float* k  = (const float*)d_in[1];
    const float* v  = (const float*)d_in[2];
    const int*   vm = (const int*)d_in[3];
    const int*   qm = (const int*)d_in[4];
    const float* Wq = (const float*)d_in[5];
    const float* bq = (const float*)d_in[6];
    const float* Wk = (const float*)d_in[7];
    const float* bk = (const float*)d_in[8];
    const float* Wv = (const float*)d_in[9];
    const float* bv = (const float*)d_in[10];
    float* out = (float*)d_out;

    __half *gxq, *gxk, *gxv, *gwq, *gwk, *gwv;
    cudaGetSymbolAddress((void**)&gxq, g_xq);
    cudaGetSymbolAddress((void**)&gxk, g_xk);
    cudaGetSymbolAddress((void**)&gxv, g_xv);
    cudaGetSymbolAddress((void**)&gwq, g_wq);
    cudaGetSymbolAddress((void**)&gwk, g_wk);
    cudaGetSymbolAddress((void**)&gwv, g_wv);

    cvt_kernel<<<dim3(XN/(256*8), 1, 3), 256>>>(q, k, v, gxq, gxk, gxv);
    cvt_kernel<<<dim3(WN/(256*8), 1, 3), 256>>>(Wq, Wk, Wv, gwq, gwk, gwv);

    const int gsmem = GST*(128*GLDA + 32*GLDB)*2;   // 56832 B
    cudaFuncSetAttribute(gemm_kernel,
                         cudaFuncAttributeMaxDynamicSharedMemorySize, gsmem);
    dim3 gg(Bb*Ss/128, DModel/128, 3);   // (32, 8, 3)
    gemm_kernel<<<gg, 256, gsmem>>>(bq, bk, bv);

    cudaFuncSetAttribute(attn_kernel,
                         cudaFuncAttributeMaxDynamicSharedMemorySize, ASMEM);
    dim3 ag(Ss/64, Bb*Hh);               // (32, 32) = 1024 CTAs
    attn_kernel<<<ag, 128, ASMEM>>>(vm, qm, out);
}